// round 4
// baseline (speedup 1.0000x reference)
#include <cuda_runtime.h>
#include <cuda_bf16.h>

// DifferentiableHMM_Centered — GB300 sm_103a, R4: single persistent kernel.
//
// Math reduction (R1): straight-through gumbel-softmax argmax collapses to
//   norm_copy[s,j] = all_means[argmax_k(log_em_k + gumbel_k)]
//   smooth_loss    = 0.1 * 2 * (#(state[row] != state[col]) over edges×bins) / (E*Bc*3)
//
// R4: R2/R3 evidence says per-launch fixed cost ~5-8us dominates the edge
// kernel (ncu: 1-thread kernel = 4.6us; edge kernel far from any ceiling).
// So: fuse state + edge + finalize into ONE kernel with an in-kernel grid
// barrier. Residency is guaranteed by construction (148*4 blocks of 256 thr,
// __launch_bounds__(256,4) => <=64 regs, <=1024 thr/SM), so the spin barrier
// cannot deadlock. All counters are reset by the ticket winner, which can only
// execute after every block has passed the barrier and taken a ticket.

#define HALF_LOG_2PI 0.9189385332046727f
#define NSM 148
#define BLOCKS_PER_SM 4
#define NBLOCKS (NSM * BLOCKS_PER_SM)
#define NTHREADS 256

// 2048 rows x 128 u64 capacity (768B used/row). Zero-initialized at module
// load; padding never written -> XOR contributes 0 mismatches.
__device__ unsigned long long g_state[2048 * 128];
__device__ unsigned int g_count;  // mismatch total
__device__ unsigned int g_done;   // finalize ticket
__device__ unsigned int g_bar;    // grid barrier arrival counter

__device__ __forceinline__ void classify(float xv, float g0, float g1, float g2,
                                         const float* __restrict__ p,
                                         int& k, float& nv) {
    float z0 = (xv - p[0]) * p[2];
    float z1 = xv * p[3];              // middle state mean == 0
    float z2 = (xv - p[1]) * p[4];
    float l0 = fmaf(-0.5f * z0, z0, p[5]) + g0;
    float l1 = fmaf(-0.5f * z1, z1, p[6]) + g1;
    float l2 = fmaf(-0.5f * z2, z2, p[7]) + g2;
    k = 0; float best = l0; nv = p[0];
    if (l1 > best) { best = l1; k = 1; nv = 0.0f; }
    if (l2 > best) {            k = 2; nv = p[1]; }
}

__device__ __forceinline__ unsigned int mismatch16(uint4 a, uint4 b) {
    unsigned long long d0 = ((unsigned long long)(a.y ^ b.y) << 32) | (a.x ^ b.x);
    unsigned long long d1 = ((unsigned long long)(a.w ^ b.w) << 32) | (a.z ^ b.z);
    d0 = (d0 | (d0 >> 1)) & 0x5555555555555555ull;
    d1 = (d1 | (d1 >> 1)) & 0x5555555555555555ull;
    return (unsigned int)(__popcll(d0) + __popcll(d1));
}

__global__ void __launch_bounds__(NTHREADS, BLOCKS_PER_SM)
fused_kernel(const float* __restrict__ x,
             const int*   __restrict__ bin_idx,
             const int*   __restrict__ edge_index,
             const float* __restrict__ gumbel,
             const float* __restrict__ state_means,
             const float* __restrict__ log_stds,
             float*       __restrict__ out,
             float*       __restrict__ loss_out,
             int B, int Bc, int stride_bytes, int stride_u4,
             int E, long long denom) {
    __shared__ float p[8];
    __shared__ unsigned int sred[NTHREADS / 32];

    if (threadIdx.x == 0) {
        float s0 = expf(log_stds[0]) + 1e-6f;
        float s1 = expf(log_stds[1]) + 1e-6f;
        float s2 = expf(log_stds[2]) + 1e-6f;
        p[0] = state_means[0];
        p[1] = state_means[1];
        p[2] = 1.0f / s0;  p[3] = 1.0f / s1;  p[4] = 1.0f / s2;
        p[5] = -logf(s0) - HALF_LOG_2PI;
        p[6] = -logf(s1) - HALF_LOG_2PI;
        p[7] = -logf(s2) - HALF_LOG_2PI;
    }
    __syncthreads();

    // ---------------- Phase 1: state map + norm_copy (grid-stride) ----------
    int groups = (Bc + 3) >> 2;                 // 4 bins -> 1 packed byte
    int nitems = gridDim.x * (int)blockDim.x;   // total threads
    int total  = (B ? ((int)( ( (long long)Bc ) )) : 0, 0); // (unused placeholder)
    int S_items;                                 // total items = S * groups
    {
        // S derived on host side is implicit: out rows = total x rows. We pass
        // it via gridDim-independent math: x has S*B elements but we only get
        // B, Bc; host passes E/denom. Recover S from denom? No — host encodes
        // S in stride of loop below via 'n_state_items'.
    }
    // n_state_items is passed through 'denom' companions? Keep it simple:
    // host packs S into high bits of stride_bytes? No — pass explicitly:
    // (see extra param trick below: we smuggle S via B? B==Bc here, so we
    //  pass S as stride_bytes>>16? Too clever.)
    // --- S is passed as an explicit kernel parameter instead: ---
    // (signature kept; S recovered from 'E' companions is wrong; so we use
    //  the fact that host passes n_state_items in 'B' when B==Bc.)
    // NOTE: to stay honest, host passes n_state_items via 'B' ONLY when the
    // bin map is the identity-covering case; otherwise B != Bc is impossible
    // here since in_sizes gives x as S*B with B==Bc. We therefore pass S
    // separately packed in the unused upper half of stride_bytes.
    int S = stride_bytes >> 16;
    stride_bytes &= 0xffff;
    S_items = S * groups;

    for (int item = blockIdx.x * (int)blockDim.x + threadIdx.x;
         item < S_items; item += nitems) {
        int s  = item / groups;
        int jt = item - s * groups;
        int j0 = jt << 2;

        unsigned int pack = 0;
        float nv0 = 0.f, nv1 = 0.f, nv2 = 0.f, nv3 = 0.f;
        bool full = (j0 + 3 < Bc);
        bool fast = false;
        int src0 = __ldg(bin_idx + j0);
        size_t base = (size_t)s * (size_t)B + (size_t)src0;

        if (full) {
            int src1 = __ldg(bin_idx + j0 + 1);
            int src2 = __ldg(bin_idx + j0 + 2);
            int src3 = __ldg(bin_idx + j0 + 3);
            fast = (src1 == src0 + 1) && (src2 == src0 + 2) &&
                   (src3 == src0 + 3) && ((base & 3) == 0);
            if (fast) {
                float4 xv = __ldg((const float4*)(x + base));
                const float4* g4 = (const float4*)(gumbel + base * 3u);
                float4 ga = __ldg(g4), gb = __ldg(g4 + 1), gc = __ldg(g4 + 2);
                int k;
                classify(xv.x, ga.x, ga.y, ga.z, p, k, nv0); pack  = (unsigned)k;
                classify(xv.y, ga.w, gb.x, gb.y, p, k, nv1); pack |= (unsigned)k << 2;
                classify(xv.z, gb.z, gb.w, gc.x, p, k, nv2); pack |= (unsigned)k << 4;
                classify(xv.w, gc.y, gc.z, gc.w, p, k, nv3); pack |= (unsigned)k << 6;
            }
        }
        if (!fast) {
            float nv[4] = {0.f, 0.f, 0.f, 0.f};
            for (int u = 0; u < 4; ++u) {
                int j = j0 + u;
                if (j >= Bc) break;
                int src = __ldg(bin_idx + j);
                size_t xi = (size_t)s * (size_t)B + (size_t)src;
                float xv = __ldg(x + xi);
                const float* g = gumbel + xi * 3u;
                int k;
                classify(xv, __ldg(g), __ldg(g + 1), __ldg(g + 2), p, k, nv[u]);
                pack |= (unsigned)k << (2 * u);
            }
            nv0 = nv[0]; nv1 = nv[1]; nv2 = nv[2]; nv3 = nv[3];
        }

        size_t oi = (size_t)s * (size_t)Bc + (size_t)j0;
        if (full && ((oi & 3) == 0)) {
            *(float4*)(out + oi) = make_float4(nv0, nv1, nv2, nv3);
        } else {
            if (j0 + 0 < Bc) out[oi + 0] = nv0;
            if (j0 + 1 < Bc) out[oi + 1] = nv1;
            if (j0 + 2 < Bc) out[oi + 2] = nv2;
            if (j0 + 3 < Bc) out[oi + 3] = nv3;
        }
        ((unsigned char*)g_state)[(size_t)s * (size_t)stride_bytes + (size_t)jt] =
            (unsigned char)pack;
    }

    // ---------------- Grid barrier (all blocks resident by construction) ----
    __syncthreads();
    if (threadIdx.x == 0) {
        __threadfence();                         // release state writes
        unsigned int a = atomicAdd(&g_bar, 1u) + 1u;
        if (a < gridDim.x) {
            volatile unsigned int* vb = &g_bar;
            while (*vb < gridDim.x) { }
        }
        __threadfence();                         // acquire before state reads
    }
    __syncthreads();

    // ---------------- Phase 2: edge mismatch count (warp grid-stride) -------
    int warp = threadIdx.x >> 5;
    int lane = threadIdx.x & 31;
    int warps_per_block = (int)blockDim.x >> 5;
    int gwarp  = blockIdx.x * warps_per_block + warp;
    int nwarps = gridDim.x * warps_per_block;

    unsigned int cnt = 0;
    for (int e = gwarp; e < E; e += nwarps) {
        int r = __ldg(edge_index + e);
        int c = __ldg(edge_index + E + e);
        if (r == c) continue;
        const uint4* a = (const uint4*)g_state + (size_t)r * (size_t)stride_u4;
        const uint4* b = (const uint4*)g_state + (size_t)c * (size_t)stride_u4;
        if (stride_u4 <= 64) {
            bool p1 = lane + 32 < stride_u4;     // lane < stride_u4 always (>=32)
            uint4 va0 = __ldg(a + lane), vb0 = __ldg(b + lane);
            uint4 va1 = make_uint4(0,0,0,0), vb1 = va1;
            if (p1) { va1 = __ldg(a + lane + 32); vb1 = __ldg(b + lane + 32); }
            cnt += mismatch16(va0, vb0);
            if (p1) cnt += mismatch16(va1, vb1);
        } else {
            for (int w = lane; w < stride_u4; w += 32)
                cnt += mismatch16(__ldg(a + w), __ldg(b + w));
        }
    }
    cnt = __reduce_add_sync(0xffffffffu, cnt);
    if (lane == 0) sred[warp] = cnt;
    __syncthreads();

    // ---------------- Finalize (ticketed; winner writes loss + resets) ------
    if (threadIdx.x == 0) {
        unsigned int tot = 0;
        for (int i = 0; i < warps_per_block; ++i) tot += sred[i];
        if (tot) atomicAdd(&g_count, tot);
        __threadfence();
        unsigned int ticket = atomicAdd(&g_done, 1u);
        if (ticket == gridDim.x - 1u) {
            unsigned int totalc = atomicAdd(&g_count, 0u);   // ordered read
            loss_out[0] = (float)(0.2 * (double)totalc / (double)denom);
            g_count = 0u;            // reset for next graph replay
            g_done  = 0u;
            g_bar   = 0u;
        }
    }
}

extern "C" void kernel_launch(void* const* d_in, const int* in_sizes, int n_in,
                              void* d_out, int out_size) {
    const float* x           = (const float*)d_in[0];
    const int*   bin_idx     = (const int*)  d_in[1];
    const int*   edge_index  = (const int*)  d_in[2];
    const float* gumbel      = (const float*)d_in[3];
    const float* state_means = (const float*)d_in[4];
    const float* log_stds    = (const float*)d_in[5];
    float* out = (float*)d_out;

    int Bc = in_sizes[1];          // covered bins (output columns)
    int E  = in_sizes[2] / 2;      // edges
    int B  = Bc;                   // ranges cover all bins => B == Bc
    int S  = in_sizes[0] / B;      // spots

    int groups       = (Bc + 3) / 4;              // packed bytes per row
    int words        = (groups + 7) / 8;          // u64 words used
    int stride_words = (words + 15) & ~15;        // pad to 128B
    if (stride_words > 128) stride_words = 128;   // capacity guard
    int stride_bytes = stride_words * 8;          // <= 1024, fits in 16 bits
    int stride_u4    = stride_words / 2;

    long long denom = (long long)E * (long long)Bc * 3ll;
    int packed_stride = (S << 16) | stride_bytes; // S <= 2048 fits easily

    fused_kernel<<<NBLOCKS, NTHREADS>>>(
        x, bin_idx, edge_index, gumbel, state_means, log_stds,
        out, out + ((size_t)out_size - 1),
        B, Bc, packed_stride, stride_u4, E, denom);
}

// round 5
// speedup vs baseline: 1.0598x; 1.0598x over previous
#include <cuda_runtime.h>
#include <cuda_bf16.h>

// DifferentiableHMM_Centered — GB300 sm_103a, R5
//
// Math reduction (R1): straight-through gumbel-softmax argmax collapses to
//   norm_copy[s,j] = all_means[argmax_k(log_em_k + gumbel_k)]
//   smooth_loss    = 0.1 * 2 * (#mismatch(state[row],state[col]) over E x Bc) / (E*Bc*3)
//
// R5: single persistent kernel (R4) but phase 1 restructured for memory-level
// parallelism: R4 ncu showed DRAM 48% / issue 32% / occ 46% => latency-bound
// (4 outstanding loads/warp behind a dependent bin_idx load). Now: 8 bins per
// thread-iteration = 8 independent float4 loads, issued SPECULATIVELY at the
// identity address (always in-bounds: j0 < Bc <= B) in parallel with the
// bin_idx loads; generic scalar fallback if bin_idx isn't identity there.
// __ldcs/__stcs on zero-reuse streams keeps the state map L2-resident.

#define HALF_LOG_2PI 0.9189385332046727f
#define NSM 148
#define BPSM 4
#define NBLOCKS (NSM * BPSM)
#define NT 256

// 2048 rows x 128 u64 capacity (768B used/row). Zero-initialized at module
// load; padding never written -> XOR contributes 0 mismatches.
__device__ unsigned long long g_state[2048 * 128];
__device__ unsigned int g_count;  // mismatch total
__device__ unsigned int g_done;   // finalize ticket
__device__ unsigned int g_bar;    // grid barrier arrival counter

__device__ __forceinline__ void classify(float xv, float g0, float g1, float g2,
                                         const float* __restrict__ p,
                                         int& k, float& nv) {
    float z0 = (xv - p[0]) * p[2];
    float z1 = xv * p[3];              // middle state mean == 0
    float z2 = (xv - p[1]) * p[4];
    float l0 = fmaf(-0.5f * z0, z0, p[5]) + g0;
    float l1 = fmaf(-0.5f * z1, z1, p[6]) + g1;
    float l2 = fmaf(-0.5f * z2, z2, p[7]) + g2;
    k = 0; float best = l0; nv = p[0];
    if (l1 > best) { best = l1; k = 1; nv = 0.0f; }
    if (l2 > best) {            k = 2; nv = p[1]; }
}

__device__ __forceinline__ unsigned int mismatch16(uint4 a, uint4 b) {
    unsigned long long d0 = ((unsigned long long)(a.y ^ b.y) << 32) | (a.x ^ b.x);
    unsigned long long d1 = ((unsigned long long)(a.w ^ b.w) << 32) | (a.z ^ b.z);
    d0 = (d0 | (d0 >> 1)) & 0x5555555555555555ull;
    d1 = (d1 | (d1 >> 1)) & 0x5555555555555555ull;
    return (unsigned int)(__popcll(d0) + __popcll(d1));
}

__global__ void __launch_bounds__(NT, BPSM)
fused_kernel(const float* __restrict__ x,
             const int*   __restrict__ bin_idx,
             const int*   __restrict__ edge_index,
             const float* __restrict__ gumbel,
             const float* __restrict__ state_means,
             const float* __restrict__ log_stds,
             float*       __restrict__ out,
             float*       __restrict__ loss_out,
             int B, int Bc, int S, int stride_bytes, int stride_u4,
             int E, long long denom) {
    __shared__ float p[8];
    __shared__ unsigned int sred[NT / 32];

    if (threadIdx.x == 0) {
        float s0 = expf(log_stds[0]) + 1e-6f;
        float s1 = expf(log_stds[1]) + 1e-6f;
        float s2 = expf(log_stds[2]) + 1e-6f;
        p[0] = state_means[0];
        p[1] = state_means[1];
        p[2] = 1.0f / s0;  p[3] = 1.0f / s1;  p[4] = 1.0f / s2;
        p[5] = -logf(s0) - HALF_LOG_2PI;
        p[6] = -logf(s1) - HALF_LOG_2PI;
        p[7] = -logf(s2) - HALF_LOG_2PI;
    }
    __syncthreads();

    // -------- Phase 1: state map + norm_copy, 8 bins / thread-iteration -----
    int groups  = (Bc + 3) >> 2;        // 4 bins -> 1 packed byte
    int pgroups = (groups + 1) >> 1;    // byte pairs (8 bins)
    int items   = S * pgroups;
    int gstride = gridDim.x * (int)blockDim.x;

    for (int it = blockIdx.x * (int)blockDim.x + threadIdx.x;
         it < items; it += gstride) {
        int s   = it / pgroups;
        int jp  = it - s * pgroups;
        int jt0 = jp << 1;              // first packed-byte index
        int j0  = jp << 3;              // first bin index
        size_t rowx = (size_t)s * (size_t)B;
        size_t base = rowx + (size_t)j0;

        bool done = false;
        if ((j0 + 7 < Bc) && ((base & 3) == 0) && ((j0 & 7) == 0)) {
            // speculative loads (identity mapping), all independent:
            int4 bi0 = __ldg((const int4*)(bin_idx + j0));
            int4 bi1 = __ldg((const int4*)(bin_idx + j0 + 4));
            const float4* xp = (const float4*)(x + base);
            float4 xv0 = __ldcs(xp), xv1 = __ldcs(xp + 1);
            const float4* gp = (const float4*)(gumbel + base * 3u);
            float4 ga = __ldcs(gp + 0), gb = __ldcs(gp + 1), gc = __ldcs(gp + 2);
            float4 gd = __ldcs(gp + 3), ge = __ldcs(gp + 4), gf = __ldcs(gp + 5);
            bool id = (bi0.x == j0)     & (bi0.y == j0 + 1) &
                      (bi0.z == j0 + 2) & (bi0.w == j0 + 3) &
                      (bi1.x == j0 + 4) & (bi1.y == j0 + 5) &
                      (bi1.z == j0 + 6) & (bi1.w == j0 + 7);
            if (id) {
                int k; unsigned int pack = 0;
                float n0, n1, n2, n3, n4, n5, n6, n7;
                classify(xv0.x, ga.x, ga.y, ga.z, p, k, n0); pack  = (unsigned)k;
                classify(xv0.y, ga.w, gb.x, gb.y, p, k, n1); pack |= (unsigned)k << 2;
                classify(xv0.z, gb.z, gb.w, gc.x, p, k, n2); pack |= (unsigned)k << 4;
                classify(xv0.w, gc.y, gc.z, gc.w, p, k, n3); pack |= (unsigned)k << 6;
                classify(xv1.x, gd.x, gd.y, gd.z, p, k, n4); pack |= (unsigned)k << 8;
                classify(xv1.y, gd.w, ge.x, ge.y, p, k, n5); pack |= (unsigned)k << 10;
                classify(xv1.z, ge.z, ge.w, gf.x, p, k, n6); pack |= (unsigned)k << 12;
                classify(xv1.w, gf.y, gf.z, gf.w, p, k, n7); pack |= (unsigned)k << 14;

                size_t oi = (size_t)s * (size_t)Bc + (size_t)j0;
                if ((oi & 3) == 0) {
                    __stcs((float4*)(out + oi),     make_float4(n0, n1, n2, n3));
                    __stcs((float4*)(out + oi) + 1, make_float4(n4, n5, n6, n7));
                } else {
                    out[oi+0]=n0; out[oi+1]=n1; out[oi+2]=n2; out[oi+3]=n3;
                    out[oi+4]=n4; out[oi+5]=n5; out[oi+6]=n6; out[oi+7]=n7;
                }
                *(unsigned short*)((unsigned char*)g_state +
                                   (size_t)s * (size_t)stride_bytes + (size_t)jt0)
                    = (unsigned short)pack;
                done = true;
            }
        }
        if (!done) {
            // generic fallback: two packed bytes, scalar gathers
            for (int h = 0; h < 2; ++h) {
                int jt = jt0 + h;
                if (jt >= groups) break;
                int jb = jt << 2;
                unsigned int pack = 0;
                float nv[4] = {0.f, 0.f, 0.f, 0.f};
                for (int u = 0; u < 4; ++u) {
                    int j = jb + u;
                    if (j >= Bc) break;
                    int src = __ldg(bin_idx + j);
                    size_t xi = rowx + (size_t)src;
                    float xv = __ldg(x + xi);
                    const float* g = gumbel + xi * 3u;
                    int k;
                    classify(xv, __ldg(g), __ldg(g+1), __ldg(g+2), p, k, nv[u]);
                    pack |= (unsigned)k << (2 * u);
                }
                size_t oi = (size_t)s * (size_t)Bc + (size_t)jb;
                for (int u = 0; u < 4; ++u)
                    if (jb + u < Bc) out[oi + u] = nv[u];
                ((unsigned char*)g_state)[(size_t)s * (size_t)stride_bytes +
                                          (size_t)jt] = (unsigned char)pack;
            }
        }
    }

    // -------- Grid barrier (all blocks resident by construction) ------------
    __syncthreads();
    if (threadIdx.x == 0) {
        __threadfence();                         // release state writes
        unsigned int a = atomicAdd(&g_bar, 1u) + 1u;
        if (a < gridDim.x) {
            volatile unsigned int* vb = &g_bar;
            while (*vb < gridDim.x) { }
        }
        __threadfence();                         // acquire before state reads
    }
    __syncthreads();

    // -------- Phase 2: edge mismatch count (warp per edge, grid-stride) -----
    int warp = threadIdx.x >> 5;
    int lane = threadIdx.x & 31;
    int wpb  = (int)blockDim.x >> 5;
    int gwarp  = blockIdx.x * wpb + warp;
    int nwarps = gridDim.x * wpb;

    unsigned int cnt = 0;
    for (int e = gwarp; e < E; e += nwarps) {
        int r = __ldg(edge_index + e);
        int c = __ldg(edge_index + E + e);
        if (r == c) continue;
        const uint4* a = (const uint4*)g_state + (size_t)r * (size_t)stride_u4;
        const uint4* b = (const uint4*)g_state + (size_t)c * (size_t)stride_u4;
        if (stride_u4 <= 64) {
            bool p1 = lane + 32 < stride_u4;     // lane < stride_u4 (>=32) always
            uint4 va0 = __ldg(a + lane), vb0 = __ldg(b + lane);
            uint4 va1 = make_uint4(0,0,0,0), vb1 = va1;
            if (p1) { va1 = __ldg(a + lane + 32); vb1 = __ldg(b + lane + 32); }
            cnt += mismatch16(va0, vb0);
            if (p1) cnt += mismatch16(va1, vb1);
        } else {
            for (int w = lane; w < stride_u4; w += 32)
                cnt += mismatch16(__ldg(a + w), __ldg(b + w));
        }
    }
    cnt = __reduce_add_sync(0xffffffffu, cnt);
    if (lane == 0) sred[warp] = cnt;
    __syncthreads();

    // -------- Finalize (ticketed; winner writes loss + resets counters) -----
    if (threadIdx.x == 0) {
        unsigned int tot = 0;
        for (int i = 0; i < wpb; ++i) tot += sred[i];
        if (tot) atomicAdd(&g_count, tot);
        __threadfence();
        unsigned int ticket = atomicAdd(&g_done, 1u);
        if (ticket == gridDim.x - 1u) {
            unsigned int totalc = atomicAdd(&g_count, 0u);   // ordered read
            loss_out[0] = (float)(0.2 * (double)totalc / (double)denom);
            g_count = 0u;            // reset for next graph replay
            g_done  = 0u;
            g_bar   = 0u;
        }
    }
}

extern "C" void kernel_launch(void* const* d_in, const int* in_sizes, int n_in,
                              void* d_out, int out_size) {
    const float* x           = (const float*)d_in[0];
    const int*   bin_idx     = (const int*)  d_in[1];
    const int*   edge_index  = (const int*)  d_in[2];
    const float* gumbel      = (const float*)d_in[3];
    const float* state_means = (const float*)d_in[4];
    const float* log_stds    = (const float*)d_in[5];
    float* out = (float*)d_out;

    int Bc = in_sizes[1];          // covered bins (output columns)
    int E  = in_sizes[2] / 2;      // edges
    int B  = Bc;                   // ranges cover all bins => B == Bc
    int S  = in_sizes[0] / B;      // spots

    int groups       = (Bc + 3) / 4;              // packed bytes per row
    int words        = (groups + 7) / 8;          // u64 words used
    int stride_words = (words + 15) & ~15;        // pad to 128B
    if (stride_words > 128) stride_words = 128;   // capacity guard
    int stride_bytes = stride_words * 8;
    int stride_u4    = stride_words / 2;

    long long denom = (long long)E * (long long)Bc * 3ll;

    fused_kernel<<<NBLOCKS, NT>>>(
        x, bin_idx, edge_index, gumbel, state_means, log_stds,
        out, out + ((size_t)out_size - 1),
        B, Bc, S, stride_bytes, stride_u4, E, denom);
}

// round 6
// speedup vs baseline: 1.0691x; 1.0088x over previous
#include <cuda_runtime.h>
#include <cuda_bf16.h>

// DifferentiableHMM_Centered — GB300 sm_103a, R6
//
// Math reduction (R1): straight-through gumbel-softmax argmax collapses to
//   norm_copy[s,j] = all_means[argmax_k(log_em_k + gumbel_k)]
//   smooth_loss    = 0.1 * 2 * (#mismatch(state[row],state[col]) over E x Bc) / (E*Bc*3)
//
// R6: R5 was register-file-capped (regs=64 = launch_bounds cap, occ 48.5%,
// no pipe saturated => latency-bound on WARP COUNT, not per-warp MLP).
// Trade per-thread work for residency: 4 bins/thread (~40 regs) at
// __launch_bounds__(256,6) => 48 warps/SM (75% occ), 888 co-resident blocks.

#define HALF_LOG_2PI 0.9189385332046727f
#define NSM 148
#define BPSM 6
#define NBLOCKS (NSM * BPSM)
#define NT 256

// 2048 rows x 128 u64 capacity (768B used/row). Zero-initialized at module
// load; padding never written -> XOR contributes 0 mismatches.
__device__ unsigned long long g_state[2048 * 128];
__device__ unsigned int g_count;  // mismatch total
__device__ unsigned int g_done;   // finalize ticket
__device__ unsigned int g_bar;    // grid barrier arrival counter

__device__ __forceinline__ void classify(float xv, float g0, float g1, float g2,
                                         float m0, float m2,
                                         float i0, float i1, float i2,
                                         float c0, float c1, float c2,
                                         int& k, float& nv) {
    float z0 = (xv - m0) * i0;
    float z1 = xv * i1;                // middle state mean == 0
    float z2 = (xv - m2) * i2;
    float l0 = fmaf(-0.5f * z0, z0, c0) + g0;
    float l1 = fmaf(-0.5f * z1, z1, c1) + g1;
    float l2 = fmaf(-0.5f * z2, z2, c2) + g2;
    k = 0; float best = l0; nv = m0;
    if (l1 > best) { best = l1; k = 1; nv = 0.0f; }
    if (l2 > best) {            k = 2; nv = m2; }
}

__device__ __forceinline__ unsigned int mismatch16(uint4 a, uint4 b) {
    unsigned long long d0 = ((unsigned long long)(a.y ^ b.y) << 32) | (a.x ^ b.x);
    unsigned long long d1 = ((unsigned long long)(a.w ^ b.w) << 32) | (a.z ^ b.z);
    d0 = (d0 | (d0 >> 1)) & 0x5555555555555555ull;
    d1 = (d1 | (d1 >> 1)) & 0x5555555555555555ull;
    return (unsigned int)(__popcll(d0) + __popcll(d1));
}

__global__ void __launch_bounds__(NT, BPSM)
fused_kernel(const float* __restrict__ x,
             const int*   __restrict__ bin_idx,
             const int*   __restrict__ edge_index,
             const float* __restrict__ gumbel,
             const float* __restrict__ state_means,
             const float* __restrict__ log_stds,
             float*       __restrict__ out,
             float*       __restrict__ loss_out,
             int B, int Bc, int S, int stride_bytes, int stride_u4,
             int E, long long denom) {
    __shared__ float sp[8];
    __shared__ unsigned int sred[NT / 32];

    if (threadIdx.x == 0) {
        float s0 = expf(log_stds[0]) + 1e-6f;
        float s1 = expf(log_stds[1]) + 1e-6f;
        float s2 = expf(log_stds[2]) + 1e-6f;
        sp[0] = state_means[0];
        sp[1] = state_means[1];
        sp[2] = 1.0f / s0;  sp[3] = 1.0f / s1;  sp[4] = 1.0f / s2;
        sp[5] = -logf(s0) - HALF_LOG_2PI;
        sp[6] = -logf(s1) - HALF_LOG_2PI;
        sp[7] = -logf(s2) - HALF_LOG_2PI;
    }
    __syncthreads();

    // params in registers for the hot loop
    float m0 = sp[0], m2 = sp[1];
    float i0 = sp[2], i1 = sp[3], i2 = sp[4];
    float c0 = sp[5], c1 = sp[6], c2 = sp[7];

    // -------- Phase 1: state map + norm_copy, 4 bins / thread-iteration -----
    int groups  = (Bc + 3) >> 2;        // 4 bins -> 1 packed byte
    int items   = S * groups;
    int gstride = gridDim.x * (int)blockDim.x;

    for (int it = blockIdx.x * (int)blockDim.x + threadIdx.x;
         it < items; it += gstride) {
        int s  = it / groups;
        int jt = it - s * groups;
        int j0 = jt << 2;
        size_t rowx = (size_t)s * (size_t)B;
        size_t base = rowx + (size_t)j0;

        bool done = false;
        if ((j0 + 3 < Bc) && ((base & 3) == 0)) {
            // speculative identity-mapped loads, all independent:
            int4   bi = __ldg((const int4*)(bin_idx + j0));
            float4 xv = __ldcs((const float4*)(x + base));
            const float4* gp = (const float4*)(gumbel + base * 3u);
            float4 ga = __ldcs(gp), gb = __ldcs(gp + 1), gc = __ldcs(gp + 2);
            if ((bi.x == j0) & (bi.y == j0 + 1) & (bi.z == j0 + 2) &
                (bi.w == j0 + 3)) {
                int k; unsigned int pack = 0;
                float n0, n1, n2, n3;
                classify(xv.x, ga.x, ga.y, ga.z, m0,m2,i0,i1,i2,c0,c1,c2, k, n0);
                pack  = (unsigned)k;
                classify(xv.y, ga.w, gb.x, gb.y, m0,m2,i0,i1,i2,c0,c1,c2, k, n1);
                pack |= (unsigned)k << 2;
                classify(xv.z, gb.z, gb.w, gc.x, m0,m2,i0,i1,i2,c0,c1,c2, k, n2);
                pack |= (unsigned)k << 4;
                classify(xv.w, gc.y, gc.z, gc.w, m0,m2,i0,i1,i2,c0,c1,c2, k, n3);
                pack |= (unsigned)k << 6;

                size_t oi = (size_t)s * (size_t)Bc + (size_t)j0;
                if ((oi & 3) == 0) {
                    __stcs((float4*)(out + oi), make_float4(n0, n1, n2, n3));
                } else {
                    out[oi+0]=n0; out[oi+1]=n1; out[oi+2]=n2; out[oi+3]=n3;
                }
                ((unsigned char*)g_state)[(size_t)s * (size_t)stride_bytes +
                                          (size_t)jt] = (unsigned char)pack;
                done = true;
            }
        }
        if (!done) {
            // generic scalar fallback
            unsigned int pack = 0;
            float nv[4] = {0.f, 0.f, 0.f, 0.f};
            for (int u = 0; u < 4; ++u) {
                int j = j0 + u;
                if (j >= Bc) break;
                int src = __ldg(bin_idx + j);
                size_t xi = rowx + (size_t)src;
                float xv = __ldg(x + xi);
                const float* g = gumbel + xi * 3u;
                int k;
                classify(xv, __ldg(g), __ldg(g+1), __ldg(g+2),
                         m0,m2,i0,i1,i2,c0,c1,c2, k, nv[u]);
                pack |= (unsigned)k << (2 * u);
            }
            size_t oi = (size_t)s * (size_t)Bc + (size_t)j0;
            for (int u = 0; u < 4; ++u)
                if (j0 + u < Bc) out[oi + u] = nv[u];
            ((unsigned char*)g_state)[(size_t)s * (size_t)stride_bytes +
                                      (size_t)jt] = (unsigned char)pack;
        }
    }

    // -------- Grid barrier (all blocks resident by construction) ------------
    __syncthreads();
    if (threadIdx.x == 0) {
        __threadfence();                         // release state writes
        unsigned int a = atomicAdd(&g_bar, 1u) + 1u;
        if (a < gridDim.x) {
            volatile unsigned int* vb = &g_bar;
            while (*vb < gridDim.x) { }
        }
        __threadfence();                         // acquire before state reads
    }
    __syncthreads();

    // -------- Phase 2: edge mismatch count (warp per edge, grid-stride) -----
    int warp = threadIdx.x >> 5;
    int lane = threadIdx.x & 31;
    int wpb  = (int)blockDim.x >> 5;
    int gwarp  = blockIdx.x * wpb + warp;
    int nwarps = gridDim.x * wpb;

    unsigned int cnt = 0;
    for (int e = gwarp; e < E; e += nwarps) {
        int r = __ldg(edge_index + e);
        int c = __ldg(edge_index + E + e);
        if (r == c) continue;
        const uint4* a = (const uint4*)g_state + (size_t)r * (size_t)stride_u4;
        const uint4* b = (const uint4*)g_state + (size_t)c * (size_t)stride_u4;
        if (stride_u4 <= 64) {
            bool p1 = lane + 32 < stride_u4;     // lane < stride_u4 (>=32) always
            uint4 va0 = __ldg(a + lane), vb0 = __ldg(b + lane);
            uint4 va1 = make_uint4(0,0,0,0), vb1 = va1;
            if (p1) { va1 = __ldg(a + lane + 32); vb1 = __ldg(b + lane + 32); }
            cnt += mismatch16(va0, vb0);
            if (p1) cnt += mismatch16(va1, vb1);
        } else {
            for (int w = lane; w < stride_u4; w += 32)
                cnt += mismatch16(__ldg(a + w), __ldg(b + w));
        }
    }
    cnt = __reduce_add_sync(0xffffffffu, cnt);
    if (lane == 0) sred[warp] = cnt;
    __syncthreads();

    // -------- Finalize (ticketed; winner writes loss + resets counters) -----
    if (threadIdx.x == 0) {
        unsigned int tot = 0;
        for (int i = 0; i < wpb; ++i) tot += sred[i];
        if (tot) atomicAdd(&g_count, tot);
        __threadfence();
        unsigned int ticket = atomicAdd(&g_done, 1u);
        if (ticket == gridDim.x - 1u) {
            unsigned int totalc = atomicAdd(&g_count, 0u);   // ordered read
            loss_out[0] = (float)(0.2 * (double)totalc / (double)denom);
            g_count = 0u;            // reset for next graph replay
            g_done  = 0u;
            g_bar   = 0u;
        }
    }
}

extern "C" void kernel_launch(void* const* d_in, const int* in_sizes, int n_in,
                              void* d_out, int out_size) {
    const float* x           = (const float*)d_in[0];
    const int*   bin_idx     = (const int*)  d_in[1];
    const int*   edge_index  = (const int*)  d_in[2];
    const float* gumbel      = (const float*)d_in[3];
    const float* state_means = (const float*)d_in[4];
    const float* log_stds    = (const float*)d_in[5];
    float* out = (float*)d_out;

    int Bc = in_sizes[1];          // covered bins (output columns)
    int E  = in_sizes[2] / 2;      // edges
    int B  = Bc;                   // ranges cover all bins => B == Bc
    int S  = in_sizes[0] / B;      // spots

    int groups       = (Bc + 3) / 4;              // packed bytes per row
    int words        = (groups + 7) / 8;          // u64 words used
    int stride_words = (words + 15) & ~15;        // pad to 128B
    if (stride_words > 128) stride_words = 128;   // capacity guard
    int stride_bytes = stride_words * 8;
    int stride_u4    = stride_words / 2;

    long long denom = (long long)E * (long long)Bc * 3ll;

    fused_kernel<<<NBLOCKS, NT>>>(
        x, bin_idx, edge_index, gumbel, state_means, log_stds,
        out, out + ((size_t)out_size - 1),
        B, Bc, S, stride_bytes, stride_u4, E, denom);
}